// round 1
// baseline (speedup 1.0000x reference)
#include <cuda_runtime.h>
#include <math.h>

#define NB 16
#define NT 512
#define NH 1024
#define NL 8192
#define ND 256

// Scratch: K,V stored TRANSPOSED per batch: [b][d][t] so the attention kernel's
// B-operand tiles (k-major) load directly with float4, no runtime transpose.
__device__ float g_K[NB * ND * NT];
__device__ float g_V[NB * ND * NT];

__device__ __forceinline__ void ld8(float* r, const float* p) {
    float4 v0 = *(const float4*)p;
    float4 v1 = *(const float4*)(p + 4);
    r[0] = v0.x; r[1] = v0.y; r[2] = v0.z; r[3] = v0.w;
    r[4] = v1.x; r[5] = v1.y; r[6] = v1.z; r[7] = v1.w;
}

// ---------------------------------------------------------------------------
// Kernel 1: K/V projection.  C[bt][n] = sum_h X[bt][h] * W[n][h],
// n in [0,512): n<256 -> Wk (writes g_K), else Wv (writes g_V).
// Output written transposed: g_K[b][d][t].
// grid (64, 4), block 256, 128x128 tile, kc=32, 8x8 per thread.
// ---------------------------------------------------------------------------
__global__ __launch_bounds__(256, 1) void kv_kernel(
    const float* __restrict__ X,
    const float* __restrict__ Wk,
    const float* __restrict__ Wv)
{
    __shared__ __align__(16) float As[32][132];
    __shared__ __align__(16) float Bs[32][132];

    const int m0  = blockIdx.x * 128;      // bt tile
    const int n0  = blockIdx.y * 128;      // output-feature tile over 512
    const int tid = threadIdx.x;
    const int ty  = tid >> 4;              // 0..15 -> rows (bt)
    const int tx  = tid & 15;              // 0..15 -> cols (n)

    const float* Wbase = (n0 < 256) ? Wk : Wv;   // uniform per block (128 | 256)
    const int    nb    = n0 & 255;
    float*       dst   = (n0 < 256) ? g_K : g_V;

    float acc[8][8];
#pragma unroll
    for (int i = 0; i < 8; i++)
#pragma unroll
        for (int j = 0; j < 8; j++) acc[i][j] = 0.f;

    for (int h0 = 0; h0 < NH; h0 += 32) {
        __syncthreads();
        // Load + transpose 128x32 tiles of X and W into k-major smem.
#pragma unroll
        for (int r = 0; r < 4; r++) {
            int v = tid + r * 256;         // [0,1024)
            int m = v >> 3;                // row within tile
            int q = v & 7;                 // float4 index along h
            float4 x = *(const float4*)&X[(m0 + m) * NH + h0 + q * 4];
            As[q * 4 + 0][m] = x.x; As[q * 4 + 1][m] = x.y;
            As[q * 4 + 2][m] = x.z; As[q * 4 + 3][m] = x.w;
            float4 w = *(const float4*)&Wbase[(nb + m) * NH + h0 + q * 4];
            Bs[q * 4 + 0][m] = w.x; Bs[q * 4 + 1][m] = w.y;
            Bs[q * 4 + 2][m] = w.z; Bs[q * 4 + 3][m] = w.w;
        }
        __syncthreads();
#pragma unroll
        for (int kk = 0; kk < 32; kk++) {
            float a[8], b[8];
            ld8(a, &As[kk][ty * 8]);
            ld8(b, &Bs[kk][tx * 8]);
#pragma unroll
            for (int i = 0; i < 8; i++)
#pragma unroll
                for (int j = 0; j < 8; j++)
                    acc[i][j] = fmaf(a[i], b[j], acc[i][j]);
        }
    }

#pragma unroll
    for (int i = 0; i < 8; i++) {
        int m = m0 + ty * 8 + i;
        int b = m >> 9;          // /512
        int t = m & 511;
#pragma unroll
        for (int j = 0; j < 8; j++) {
            int n = nb + tx * 8 + j;
            dst[(b * ND + n) * NT + t] = acc[i][j];
        }
    }
}

// ---------------------------------------------------------------------------
// Kernel 2: fused dual-GEMM + flash softmax + weighted combine.
// Per CTA: batch b, 128-label tile. For each 128-wide T chunk compute
//   S[l][t] = q_l . K[b,t]      (from Qs x Ks)
//   U[l][t] = w_l . V[b,t]      (from Ws x Vs)
// then flash-accumulate (m, den, num = sum e^{s}*u) per thread (8 labels x 8 t-cols),
// merge 16 column partials per label at the end.
// grid (64, 16), block 256, kc=16, 8x8 per thread per matrix.
// ---------------------------------------------------------------------------
__global__ __launch_bounds__(256, 1) void attn_kernel(
    const float* __restrict__ Q,      // queries [L, D]
    const float* __restrict__ W,      // out_weight [L, D]
    const float* __restrict__ bias,   // [L]
    const int*   __restrict__ mask,   // [B, T]
    float*       __restrict__ out)    // [B, L]
{
    __shared__ __align__(16) float pool[4 * 16 * 132];   // 4 tiles; reused for reduction
    __shared__ int msk[128];

    float (*Qs)[132] = (float(*)[132])(pool);
    float (*Ws)[132] = (float(*)[132])(pool + 16 * 132);
    float (*Ks)[132] = (float(*)[132])(pool + 2 * 16 * 132);
    float (*Vs)[132] = (float(*)[132])(pool + 3 * 16 * 132);

    const int l0  = blockIdx.x * 128;
    const int b   = blockIdx.y;
    const int tid = threadIdx.x;
    const int ty  = tid >> 4;   // label group
    const int tx  = tid & 15;   // t-column group
    const float scale = 0.0625f;   // 1/sqrt(256)

    float m8[8], dn8[8], nm8[8];
#pragma unroll
    for (int i = 0; i < 8; i++) { m8[i] = -1e30f; dn8[i] = 0.f; nm8[i] = 0.f; }

    for (int t0 = 0; t0 < NT; t0 += 128) {
        __syncthreads();                       // protect msk/pool from prev iter readers
        if (tid < 128) msk[tid] = mask[b * NT + t0 + tid];

        float sa[8][8], ua[8][8];
#pragma unroll
        for (int i = 0; i < 8; i++)
#pragma unroll
            for (int j = 0; j < 8; j++) { sa[i][j] = 0.f; ua[i][j] = 0.f; }

        for (int d0 = 0; d0 < ND; d0 += 16) {
            __syncthreads();
            // A tiles (queries / out_weight): transpose 128x16 -> k-major
#pragma unroll
            for (int r = 0; r < 2; r++) {
                int v = tid + r * 256;         // [0,512)
                int l = v >> 2;
                int q = v & 3;
                float4 x = *(const float4*)&Q[(l0 + l) * ND + d0 + q * 4];
                Qs[q * 4 + 0][l] = x.x; Qs[q * 4 + 1][l] = x.y;
                Qs[q * 4 + 2][l] = x.z; Qs[q * 4 + 3][l] = x.w;
                float4 w = *(const float4*)&W[(l0 + l) * ND + d0 + q * 4];
                Ws[q * 4 + 0][l] = w.x; Ws[q * 4 + 1][l] = w.y;
                Ws[q * 4 + 2][l] = w.z; Ws[q * 4 + 3][l] = w.w;
            }
            // B tiles (K^T / V^T): already k-major in gmem, direct float4 copy
#pragma unroll
            for (int r = 0; r < 2; r++) {
                int v  = tid + r * 256;        // [0,512)
                int kk = v >> 5;
                int q  = v & 31;
                *(float4*)&Ks[kk][q * 4] =
                    *(const float4*)&g_K[(b * ND + d0 + kk) * NT + t0 + q * 4];
                *(float4*)&Vs[kk][q * 4] =
                    *(const float4*)&g_V[(b * ND + d0 + kk) * NT + t0 + q * 4];
            }
            __syncthreads();
#pragma unroll
            for (int kk = 0; kk < 16; kk++) {
                float a1[8], a2[8], b1[8], b2[8];
                ld8(a1, &Qs[kk][ty * 8]);
                ld8(a2, &Ws[kk][ty * 8]);
                ld8(b1, &Ks[kk][tx * 8]);
                ld8(b2, &Vs[kk][tx * 8]);
#pragma unroll
                for (int i = 0; i < 8; i++)
#pragma unroll
                    for (int j = 0; j < 8; j++) {
                        sa[i][j] = fmaf(a1[i], b1[j], sa[i][j]);
                        ua[i][j] = fmaf(a2[i], b2[j], ua[i][j]);
                    }
            }
        }

        // Flash-softmax chunk update (msk store ordered by the d-loop's syncs).
        int mv[8];
#pragma unroll
        for (int j = 0; j < 8; j++) mv[j] = msk[tx * 8 + j];
#pragma unroll
        for (int i = 0; i < 8; i++) {
            float cm = m8[i];
#pragma unroll
            for (int j = 0; j < 8; j++)
                if (mv[j]) cm = fmaxf(cm, sa[i][j] * scale);
            if (cm > m8[i]) {
                float f = __expf(m8[i] - cm);
                dn8[i] *= f; nm8[i] *= f; m8[i] = cm;
            }
#pragma unroll
            for (int j = 0; j < 8; j++) {
                if (mv[j]) {
                    float p = __expf(sa[i][j] * scale - m8[i]);
                    dn8[i] += p;
                    nm8[i] += p * ua[i][j];
                }
            }
        }
    }

    // Merge 16 column partials per label. Reuse tile smem.
    __syncthreads();
#pragma unroll
    for (int i = 0; i < 8; i++) {
        int l = ty * 8 + i;
        pool[l * 16 + tx]        = m8[i];
        pool[2048 + l * 16 + tx] = dn8[i];
        pool[4096 + l * 16 + tx] = nm8[i];
    }
    __syncthreads();
    if (tid < 128) {
        float mm = -1e30f;
#pragma unroll
        for (int c = 0; c < 16; c++) mm = fmaxf(mm, pool[tid * 16 + c]);
        float dn = 0.f, nm = 0.f;
#pragma unroll
        for (int c = 0; c < 16; c++) {
            float f = __expf(pool[tid * 16 + c] - mm);
            dn += pool[2048 + tid * 16 + c] * f;
            nm += pool[4096 + tid * 16 + c] * f;
        }
        out[b * NL + l0 + tid] = nm / dn + bias[l0 + tid];
    }
}

extern "C" void kernel_launch(void* const* d_in, const int* in_sizes, int n_in,
                              void* d_out, int out_size) {
    const float* X       = (const float*)d_in[0];
    const int*   mask    = (const int*)  d_in[1];
    const float* queries = (const float*)d_in[2];
    const float* Wk      = (const float*)d_in[3];
    const float* Wv      = (const float*)d_in[4];
    const float* outw    = (const float*)d_in[5];
    const float* bias    = (const float*)d_in[6];
    float* out = (float*)d_out;

    dim3 g1(64, 4);
    kv_kernel<<<g1, 256>>>(X, Wk, Wv);

    dim3 g2(64, 16);
    attn_kernel<<<g2, 256>>>(queries, outw, bias, mask, out);
}